// round 2
// baseline (speedup 1.0000x reference)
#include <cuda_runtime.h>
#include <cuda_bf16.h>

#define NN 50000
#define EE 800000
#define INF 128
#define HIDF 128
#define OUTF 64

// ---------------- scratch (__device__ globals; no allocation allowed) ------
__device__ float4 g_support0[NN * HIDF / 4];   // x @ W0
__device__ float4 g_h[NN * HIDF / 4];          // relu(spmm0 + b0)
__device__ float4 g_support1[NN * OUTF / 4];   // h @ W1
__device__ int    g_cnt0[NN];
__device__ int    g_cnt1[NN];
__device__ int    g_ptr0[NN + 1];
__device__ int    g_ptr1[NN + 1];
__device__ int    g_cur0[NN];
__device__ int    g_cur1[NN];
__device__ int    g_scol0[EE];
__device__ float  g_sval0[EE];
__device__ int    g_scol1[EE];
__device__ float  g_sval1[EE];

// ---------------- zero counters -------------------------------------------
__global__ void zero_counts_kernel() {
    int i = blockIdx.x * blockDim.x + threadIdx.x;
    if (i < NN) { g_cnt0[i] = 0; g_cnt1[i] = 0; }
}

// ---------------- histogram of row indices --------------------------------
__global__ void hist_kernel(const int* __restrict__ row0,
                            const int* __restrict__ row1) {
    int i = blockIdx.x * blockDim.x + threadIdx.x;
    if (i < EE) {
        atomicAdd(&g_cnt0[row0[i]], 1);
        atomicAdd(&g_cnt1[row1[i]], 1);
    }
}

// ---------------- single-block exclusive scan (n = 50000) ------------------
__global__ void scan_kernel(int which) {
    const int* __restrict__ cnt = which ? g_cnt1 : g_cnt0;
    int* __restrict__ ptr = which ? g_ptr1 : g_ptr0;
    int* __restrict__ cur = which ? g_cur1 : g_cur0;
    const int n = NN;
    __shared__ int sums[1024];
    int tid = threadIdx.x;
    int chunk = (n + 1023) / 1024;
    int begin = tid * chunk;
    int end = begin + chunk; if (end > n) end = n;
    if (begin > n) begin = n;
    int s = 0;
    for (int i = begin; i < end; i++) s += cnt[i];
    sums[tid] = s;
    __syncthreads();
    // Hillis-Steele inclusive scan
    for (int off = 1; off < 1024; off <<= 1) {
        int v = 0;
        if (tid >= off) v = sums[tid - off];
        __syncthreads();
        sums[tid] += v;
        __syncthreads();
    }
    int run = sums[tid] - s;   // exclusive prefix for this thread's chunk
    for (int i = begin; i < end; i++) {
        ptr[i] = run;
        cur[i] = run;
        run += cnt[i];
    }
    if (tid == 1023) ptr[n] = sums[1023];
}

// ---------------- counting-sort scatter of (col,val) by row ----------------
__global__ void scatter_kernel(const int* __restrict__ row,
                               const int* __restrict__ col,
                               const float* __restrict__ val,
                               int which) {
    int* __restrict__ cur  = which ? g_cur1  : g_cur0;
    int* __restrict__ scol = which ? g_scol1 : g_scol0;
    float* __restrict__ sval = which ? g_sval1 : g_sval0;
    int i = blockIdx.x * blockDim.x + threadIdx.x;
    if (i < EE) {
        int r = row[i];
        int p = atomicAdd(&cur[r], 1);
        scol[p] = col[i];
        sval[p] = val[i];
    }
}

// ---------------- tiled fp32 GEMM core (device function) -------------------
// BM=64, BN=64, BK=16, 256 threads, 4x4 register tile.
__device__ __forceinline__ void gemm_body(const float* __restrict__ A,
                                          const float* __restrict__ B,
                                          float* __restrict__ C,
                                          int M, int N, int K) {
    __shared__ __align__(16) float As[16][64];
    __shared__ __align__(16) float Bs[16][64];
    int tid = threadIdx.x;            // 256
    int tx = tid & 15;
    int ty = tid >> 4;
    int block_row = blockIdx.x * 64;
    int block_col = blockIdx.y * 64;

    float acc[4][4];
#pragma unroll
    for (int i = 0; i < 4; i++)
#pragma unroll
        for (int j = 0; j < 4; j++) acc[i][j] = 0.f;

    int ar = tid >> 2;                // 0..63
    int ak = (tid & 3) << 2;          // 0,4,8,12
    int br = tid >> 4;                // 0..15
    int bn = (tid & 15) << 2;         // 0..60

    for (int kt = 0; kt < K; kt += 16) {
        float4 a4 = make_float4(0.f, 0.f, 0.f, 0.f);
        int arow = block_row + ar;
        if (arow < M) a4 = *(const float4*)&A[arow * K + kt + ak];
        float4 b4 = *(const float4*)&B[(kt + br) * N + block_col + bn];
        __syncthreads();
        As[ak + 0][ar] = a4.x;
        As[ak + 1][ar] = a4.y;
        As[ak + 2][ar] = a4.z;
        As[ak + 3][ar] = a4.w;
        *(float4*)&Bs[br][bn] = b4;
        __syncthreads();
#pragma unroll
        for (int k = 0; k < 16; k++) {
            float4 av = *(const float4*)&As[k][ty * 4];
            float4 bv = *(const float4*)&Bs[k][tx * 4];
            acc[0][0] += av.x * bv.x; acc[0][1] += av.x * bv.y;
            acc[0][2] += av.x * bv.z; acc[0][3] += av.x * bv.w;
            acc[1][0] += av.y * bv.x; acc[1][1] += av.y * bv.y;
            acc[1][2] += av.y * bv.z; acc[1][3] += av.y * bv.w;
            acc[2][0] += av.z * bv.x; acc[2][1] += av.z * bv.y;
            acc[2][2] += av.z * bv.z; acc[2][3] += av.z * bv.w;
            acc[3][0] += av.w * bv.x; acc[3][1] += av.w * bv.y;
            acc[3][2] += av.w * bv.z; acc[3][3] += av.w * bv.w;
        }
    }
#pragma unroll
    for (int i = 0; i < 4; i++) {
        int row = block_row + ty * 4 + i;
        if (row < M) {
            float4 o = make_float4(acc[i][0], acc[i][1], acc[i][2], acc[i][3]);
            *(float4*)&C[row * N + block_col + tx * 4] = o;
        }
    }
}

// GEMM 0: support0 = x @ W0   [NN,INF] x [INF,HIDF]
__global__ void gemm0_kernel(const float* __restrict__ x,
                             const float* __restrict__ W0) {
    gemm_body(x, W0, (float*)g_support0, NN, HIDF, INF);
}

// GEMM 1: support1 = h @ W1   [NN,HIDF] x [HIDF,OUTF]
__global__ void gemm1_kernel(const float* __restrict__ W1) {
    gemm_body((const float*)g_h, W1, (float*)g_support1, NN, OUTF, HIDF);
}

// ---------------- CSR row-gather SpMM, F=128 (float4/lane), bias+relu ------
__global__ void spmm128_kernel(const float* __restrict__ bias) {
    int gtid = blockIdx.x * blockDim.x + threadIdx.x;
    int r = gtid >> 5;
    int lane = gtid & 31;
    if (r >= NN) return;
    int s = g_ptr0[r], e = g_ptr0[r + 1];
    float4 acc = make_float4(0.f, 0.f, 0.f, 0.f);
    for (int i = s; i < e; i++) {
        int c = __ldg(&g_scol0[i]);
        float v = __ldg(&g_sval0[i]);
        float4 t = __ldg(&g_support0[c * 32 + lane]);
        acc.x += v * t.x; acc.y += v * t.y;
        acc.z += v * t.z; acc.w += v * t.w;
    }
    float4 b = ((const float4*)bias)[lane];
    acc.x += b.x; acc.y += b.y; acc.z += b.z; acc.w += b.w;
    acc.x = fmaxf(acc.x, 0.f); acc.y = fmaxf(acc.y, 0.f);
    acc.z = fmaxf(acc.z, 0.f); acc.w = fmaxf(acc.w, 0.f);
    g_h[r * 32 + lane] = acc;
}

// ---------------- CSR row-gather SpMM, F=64 (float2/lane), bias ------------
__global__ void spmm64_kernel(const float* __restrict__ bias,
                              float2* __restrict__ out2) {
    int gtid = blockIdx.x * blockDim.x + threadIdx.x;
    int r = gtid >> 5;
    int lane = gtid & 31;
    if (r >= NN) return;
    int s = g_ptr1[r], e = g_ptr1[r + 1];
    const float2* __restrict__ S2 = (const float2*)g_support1;
    float2 acc = make_float2(0.f, 0.f);
    for (int i = s; i < e; i++) {
        int c = __ldg(&g_scol1[i]);
        float v = __ldg(&g_sval1[i]);
        float2 t = __ldg(&S2[c * 32 + lane]);
        acc.x += v * t.x; acc.y += v * t.y;
    }
    float2 b = ((const float2*)bias)[lane];
    acc.x += b.x; acc.y += b.y;
    out2[r * 32 + lane] = acc;
}

// ---------------- launch ---------------------------------------------------
extern "C" void kernel_launch(void* const* d_in, const int* in_sizes, int n_in,
                              void* d_out, int out_size) {
    const float* x    = (const float*)d_in[0];
    const int*   row0 = (const int*)d_in[1];
    const int*   col0 = (const int*)d_in[2];
    const float* val0 = (const float*)d_in[3];
    const int*   row1 = (const int*)d_in[4];
    const int*   col1 = (const int*)d_in[5];
    const float* val1 = (const float*)d_in[6];
    const float* W0   = (const float*)d_in[7];
    const float* b0   = (const float*)d_in[8];
    const float* W1   = (const float*)d_in[9];
    const float* b1   = (const float*)d_in[10];
    float* out = (float*)d_out;

    const int TB = 256;

    // 1) zero counters
    zero_counts_kernel<<<(NN + TB - 1) / TB, TB>>>();

    // 2) histograms (both layers in one kernel)
    hist_kernel<<<(EE + TB - 1) / TB, TB>>>(row0, row1);

    // 3) exclusive scans -> CSR ptrs (+ running cursors)
    scan_kernel<<<1, 1024>>>(0);
    scan_kernel<<<1, 1024>>>(1);

    // 4) counting-sort scatter of (col,val)
    scatter_kernel<<<(EE + TB - 1) / TB, TB>>>(row0, col0, val0, 0);
    scatter_kernel<<<(EE + TB - 1) / TB, TB>>>(row1, col1, val1, 1);

    // 5) support0 = x @ W0   [50000,128]x[128,128]
    {
        dim3 grid((NN + 63) / 64, HIDF / 64);
        gemm0_kernel<<<grid, 256>>>(x, W0);
    }

    // 6) h = relu(spmm(adj0, support0) + b0)
    spmm128_kernel<<<(NN * 32 + TB - 1) / TB, TB>>>(b0);

    // 7) support1 = h @ W1   [50000,128]x[128,64]
    {
        dim3 grid((NN + 63) / 64, OUTF / 64);
        gemm1_kernel<<<grid, 256>>>(W1);
    }

    // 8) out = spmm(adj1, support1) + b1
    spmm64_kernel<<<(NN * 32 + TB - 1) / TB, TB>>>(b1, (float2*)out);
}

// round 3
// speedup vs baseline: 1.8054x; 1.8054x over previous
#include <cuda_runtime.h>
#include <cuda_bf16.h>

#define NN 50000
#define EE 800000
#define INF 128
#define HIDF 128
#define OUTF 64

#define SCAN_BLK 512
#define NBLK ((NN + SCAN_BLK - 1) / SCAN_BLK)   // 98

// ---------------- scratch (__device__ globals; no allocation allowed) ------
__device__ float4 g_support0[NN * HIDF / 4];   // x @ W0
__device__ float4 g_h[NN * HIDF / 4];          // relu(spmm0 + b0)
__device__ float4 g_support1[NN * OUTF / 4];   // h @ W1
__device__ int    g_cnt0[NN];
__device__ int    g_cnt1[NN];
__device__ int    g_ptr0[NN + 1];
__device__ int    g_ptr1[NN + 1];
__device__ int    g_cur0[NN];
__device__ int    g_cur1[NN];
__device__ int    g_bsum[2][NBLK];
__device__ int    g_boff[2][NBLK];
__device__ int    g_scol0[EE];
__device__ float  g_sval0[EE];
__device__ int    g_scol1[EE];
__device__ float  g_sval1[EE];

// ---------------- zero counters -------------------------------------------
__global__ void zero_counts_kernel() {
    int i = blockIdx.x * blockDim.x + threadIdx.x;
    if (i < NN) { g_cnt0[i] = 0; g_cnt1[i] = 0; }
}

// ---------------- histogram of row indices --------------------------------
__global__ void hist_kernel(const int* __restrict__ row0,
                            const int* __restrict__ row1) {
    int i = blockIdx.x * blockDim.x + threadIdx.x;
    if (i < EE) {
        atomicAdd(&g_cnt0[row0[i]], 1);
        atomicAdd(&g_cnt1[row1[i]], 1);
    }
}

// ---------------- scan phase 1: block-local exclusive scan -----------------
// grid (NBLK, 2). Each block scans SCAN_BLK counts, writes exclusive
// prefixes into ptr[] (block-local) and block sum into g_bsum.
__global__ void scan_phase1_kernel() {
    __shared__ int s[SCAN_BLK];
    int which = blockIdx.y;
    const int* __restrict__ cnt = which ? g_cnt1 : g_cnt0;
    int* __restrict__ ptr = which ? g_ptr1 : g_ptr0;
    int tid = threadIdx.x;
    int i = blockIdx.x * SCAN_BLK + tid;
    int v = (i < NN) ? cnt[i] : 0;
    s[tid] = v;
    __syncthreads();
#pragma unroll
    for (int off = 1; off < SCAN_BLK; off <<= 1) {
        int t = (tid >= off) ? s[tid - off] : 0;
        __syncthreads();
        s[tid] += t;
        __syncthreads();
    }
    if (i < NN) ptr[i] = s[tid] - v;          // exclusive within block
    if (tid == SCAN_BLK - 1) g_bsum[which][blockIdx.x] = s[tid];
}

// ---------------- scan phase 2: scan the block sums (both layers) ----------
__global__ void scan_phase2_kernel() {
    __shared__ int s[128];
    int tid = threadIdx.x;
    for (int which = 0; which < 2; which++) {
        int v = (tid < NBLK) ? g_bsum[which][tid] : 0;
        s[tid] = v;
        __syncthreads();
#pragma unroll
        for (int off = 1; off < 128; off <<= 1) {
            int t = (tid >= off) ? s[tid - off] : 0;
            __syncthreads();
            s[tid] += t;
            __syncthreads();
        }
        if (tid < NBLK) g_boff[which][tid] = s[tid] - v;
        if (tid == NBLK - 1) {
            if (which) g_ptr1[NN] = s[tid];
            else       g_ptr0[NN] = s[tid];
        }
        __syncthreads();
    }
}

// ---------------- scan phase 3: add block offsets, init cursors ------------
__global__ void scan_phase3_kernel() {
    int which = blockIdx.y;
    int* __restrict__ ptr = which ? g_ptr1 : g_ptr0;
    int* __restrict__ cur = which ? g_cur1 : g_cur0;
    int i = blockIdx.x * SCAN_BLK + threadIdx.x;
    if (i < NN) {
        int v = ptr[i] + g_boff[which][blockIdx.x];
        ptr[i] = v;
        cur[i] = v;
    }
}

// ---------------- counting-sort scatter of (col,val) by row ----------------
__global__ void scatter_kernel(const int* __restrict__ row,
                               const int* __restrict__ col,
                               const float* __restrict__ val,
                               int which) {
    int* __restrict__ cur  = which ? g_cur1  : g_cur0;
    int* __restrict__ scol = which ? g_scol1 : g_scol0;
    float* __restrict__ sval = which ? g_sval1 : g_sval0;
    int i = blockIdx.x * blockDim.x + threadIdx.x;
    if (i < EE) {
        int r = row[i];
        int p = atomicAdd(&cur[r], 1);
        scol[p] = col[i];
        sval[p] = val[i];
    }
}

// ---------------- tiled fp32 GEMM core (device function) -------------------
// BM=64, BN=64, BK=16, 256 threads, 4x4 register tile.
__device__ __forceinline__ void gemm_body(const float* __restrict__ A,
                                          const float* __restrict__ B,
                                          float* __restrict__ C,
                                          int M, int N, int K) {
    __shared__ __align__(16) float As[16][64];
    __shared__ __align__(16) float Bs[16][64];
    int tid = threadIdx.x;            // 256
    int tx = tid & 15;
    int ty = tid >> 4;
    int block_row = blockIdx.x * 64;
    int block_col = blockIdx.y * 64;

    float acc[4][4];
#pragma unroll
    for (int i = 0; i < 4; i++)
#pragma unroll
        for (int j = 0; j < 4; j++) acc[i][j] = 0.f;

    int ar = tid >> 2;                // 0..63
    int ak = (tid & 3) << 2;          // 0,4,8,12
    int br = tid >> 4;                // 0..15
    int bn = (tid & 15) << 2;         // 0..60

    for (int kt = 0; kt < K; kt += 16) {
        float4 a4 = make_float4(0.f, 0.f, 0.f, 0.f);
        int arow = block_row + ar;
        if (arow < M) a4 = *(const float4*)&A[arow * K + kt + ak];
        float4 b4 = *(const float4*)&B[(kt + br) * N + block_col + bn];
        __syncthreads();
        As[ak + 0][ar] = a4.x;
        As[ak + 1][ar] = a4.y;
        As[ak + 2][ar] = a4.z;
        As[ak + 3][ar] = a4.w;
        *(float4*)&Bs[br][bn] = b4;
        __syncthreads();
#pragma unroll
        for (int k = 0; k < 16; k++) {
            float4 av = *(const float4*)&As[k][ty * 4];
            float4 bv = *(const float4*)&Bs[k][tx * 4];
            acc[0][0] += av.x * bv.x; acc[0][1] += av.x * bv.y;
            acc[0][2] += av.x * bv.z; acc[0][3] += av.x * bv.w;
            acc[1][0] += av.y * bv.x; acc[1][1] += av.y * bv.y;
            acc[1][2] += av.y * bv.z; acc[1][3] += av.y * bv.w;
            acc[2][0] += av.z * bv.x; acc[2][1] += av.z * bv.y;
            acc[2][2] += av.z * bv.z; acc[2][3] += av.z * bv.w;
            acc[3][0] += av.w * bv.x; acc[3][1] += av.w * bv.y;
            acc[3][2] += av.w * bv.z; acc[3][3] += av.w * bv.w;
        }
    }
#pragma unroll
    for (int i = 0; i < 4; i++) {
        int row = block_row + ty * 4 + i;
        if (row < M) {
            float4 o = make_float4(acc[i][0], acc[i][1], acc[i][2], acc[i][3]);
            *(float4*)&C[row * N + block_col + tx * 4] = o;
        }
    }
}

// GEMM 0: support0 = x @ W0   [NN,INF] x [INF,HIDF]
__global__ void gemm0_kernel(const float* __restrict__ x,
                             const float* __restrict__ W0) {
    gemm_body(x, W0, (float*)g_support0, NN, HIDF, INF);
}

// GEMM 1: support1 = h @ W1   [NN,HIDF] x [HIDF,OUTF]
__global__ void gemm1_kernel(const float* __restrict__ W1) {
    gemm_body((const float*)g_h, W1, (float*)g_support1, NN, OUTF, HIDF);
}

// ---------------- CSR row-gather SpMM, F=128 (float4/lane), bias+relu ------
__global__ void spmm128_kernel(const float* __restrict__ bias) {
    int gtid = blockIdx.x * blockDim.x + threadIdx.x;
    int r = gtid >> 5;
    int lane = gtid & 31;
    if (r >= NN) return;
    int s = g_ptr0[r], e = g_ptr0[r + 1];
    float4 acc = make_float4(0.f, 0.f, 0.f, 0.f);
    for (int i = s; i < e; i++) {
        int c = __ldg(&g_scol0[i]);
        float v = __ldg(&g_sval0[i]);
        float4 t = __ldg(&g_support0[c * 32 + lane]);
        acc.x += v * t.x; acc.y += v * t.y;
        acc.z += v * t.z; acc.w += v * t.w;
    }
    float4 b = ((const float4*)bias)[lane];
    acc.x += b.x; acc.y += b.y; acc.z += b.z; acc.w += b.w;
    acc.x = fmaxf(acc.x, 0.f); acc.y = fmaxf(acc.y, 0.f);
    acc.z = fmaxf(acc.z, 0.f); acc.w = fmaxf(acc.w, 0.f);
    g_h[r * 32 + lane] = acc;
}

// ---------------- CSR row-gather SpMM, F=64 (float2/lane), bias ------------
__global__ void spmm64_kernel(const float* __restrict__ bias,
                              float2* __restrict__ out2) {
    int gtid = blockIdx.x * blockDim.x + threadIdx.x;
    int r = gtid >> 5;
    int lane = gtid & 31;
    if (r >= NN) return;
    int s = g_ptr1[r], e = g_ptr1[r + 1];
    const float2* __restrict__ S2 = (const float2*)g_support1;
    float2 acc = make_float2(0.f, 0.f);
    for (int i = s; i < e; i++) {
        int c = __ldg(&g_scol1[i]);
        float v = __ldg(&g_sval1[i]);
        float2 t = __ldg(&S2[c * 32 + lane]);
        acc.x += v * t.x; acc.y += v * t.y;
    }
    float2 b = ((const float2*)bias)[lane];
    acc.x += b.x; acc.y += b.y;
    out2[r * 32 + lane] = acc;
}

// ---------------- launch ---------------------------------------------------
extern "C" void kernel_launch(void* const* d_in, const int* in_sizes, int n_in,
                              void* d_out, int out_size) {
    const float* x    = (const float*)d_in[0];
    const int*   row0 = (const int*)d_in[1];
    const int*   col0 = (const int*)d_in[2];
    const float* val0 = (const float*)d_in[3];
    const int*   row1 = (const int*)d_in[4];
    const int*   col1 = (const int*)d_in[5];
    const float* val1 = (const float*)d_in[6];
    const float* W0   = (const float*)d_in[7];
    const float* b0   = (const float*)d_in[8];
    const float* W1   = (const float*)d_in[9];
    const float* b1   = (const float*)d_in[10];
    float* out = (float*)d_out;

    const int TB = 256;

    // 1) zero counters
    zero_counts_kernel<<<(NN + TB - 1) / TB, TB>>>();

    // 2) histograms (both layers in one kernel)
    hist_kernel<<<(EE + TB - 1) / TB, TB>>>(row0, row1);

    // 3) multi-block exclusive scans -> CSR ptrs (+ running cursors)
    {
        dim3 g1(NBLK, 2);
        scan_phase1_kernel<<<g1, SCAN_BLK>>>();
        scan_phase2_kernel<<<1, 128>>>();
        scan_phase3_kernel<<<g1, SCAN_BLK>>>();
    }

    // 4) counting-sort scatter of (col,val)
    scatter_kernel<<<(EE + TB - 1) / TB, TB>>>(row0, col0, val0, 0);
    scatter_kernel<<<(EE + TB - 1) / TB, TB>>>(row1, col1, val1, 1);

    // 5) support0 = x @ W0   [50000,128]x[128,128]
    {
        dim3 grid((NN + 63) / 64, HIDF / 64);
        gemm0_kernel<<<grid, 256>>>(x, W0);
    }

    // 6) h = relu(spmm(adj0, support0) + b0)
    spmm128_kernel<<<(NN * 32 + TB - 1) / TB, TB>>>(b0);

    // 7) support1 = h @ W1   [50000,128]x[128,64]
    {
        dim3 grid((NN + 63) / 64, OUTF / 64);
        gemm1_kernel<<<grid, 256>>>(W1);
    }

    // 8) out = spmm(adj1, support1) + b1
    spmm64_kernel<<<(NN * 32 + TB - 1) / TB, TB>>>(b1, (float2*)out);
}

// round 5
// speedup vs baseline: 2.4339x; 1.3482x over previous
#include <cuda_runtime.h>
#include <cuda_bf16.h>
#include <cstdint>

#define NN 50000
#define EE 800000
#define INF 128
#define HIDF 128
#define OUTF 64

#define SCAN_BLK 512
#define NBLK ((NN + SCAN_BLK - 1) / SCAN_BLK)   // 98

// ---------------- scratch (__device__ globals; no allocation allowed) ------
__device__ float4 g_support0[NN * HIDF / 4];   // x @ W0
__device__ float4 g_h[NN * HIDF / 4];          // relu(spmm0 + b0)
__device__ float4 g_support1[NN * OUTF / 4];   // h @ W1
__device__ int    g_cnt0[NN];
__device__ int    g_cnt1[NN];
__device__ int    g_ptr0[NN + 1];
__device__ int    g_ptr1[NN + 1];
__device__ int    g_cur0[NN];
__device__ int    g_cur1[NN];
__device__ int    g_bsum[2][NBLK];
__device__ int    g_boff[2][NBLK];
__device__ int    g_scol0[EE];
__device__ float  g_sval0[EE];
__device__ int    g_scol1[EE];
__device__ float  g_sval1[EE];

// ---------------- small helpers -------------------------------------------
__device__ __forceinline__ uint32_t f2tf32(float f) {
    uint32_t r;
    asm("cvt.rna.tf32.f32 %0, %1;" : "=r"(r) : "f"(f));
    return r;
}
__device__ __forceinline__ void mma_tf32(float& c0, float& c1, float& c2, float& c3,
                                         uint32_t a0, uint32_t a1, uint32_t a2, uint32_t a3,
                                         uint32_t b0, uint32_t b1) {
    asm volatile(
        "mma.sync.aligned.m16n8k8.row.col.f32.tf32.tf32.f32 "
        "{%0,%1,%2,%3}, {%4,%5,%6,%7}, {%8,%9}, {%0,%1,%2,%3};"
        : "+f"(c0), "+f"(c1), "+f"(c2), "+f"(c3)
        : "r"(a0), "r"(a1), "r"(a2), "r"(a3), "r"(b0), "r"(b1));
}

// ---------------- zero counters -------------------------------------------
__global__ void zero_counts_kernel() {
    int i = blockIdx.x * blockDim.x + threadIdx.x;
    if (i < NN) { g_cnt0[i] = 0; g_cnt1[i] = 0; }
}

// ---------------- histogram of row indices --------------------------------
__global__ void hist_kernel(const int* __restrict__ row0,
                            const int* __restrict__ row1) {
    int i = blockIdx.x * blockDim.x + threadIdx.x;
    if (i < EE) {
        atomicAdd(&g_cnt0[row0[i]], 1);
        atomicAdd(&g_cnt1[row1[i]], 1);
    }
}

// ---------------- tf32 mma.sync GEMM: C[M,NC] = A[M,128] @ W[128,NC] -------
// CTA: 128 rows x NC cols, K=128 all in smem. 256 threads = 8 warps.
// Warp grid: 4 (m) x 2 (n): warp tile = 32 x (NC/2).
// A smem stride 132 floats (conflict-free m-fragment loads),
// B smem stride NC+8   (conflict-free k-fragment loads).
template <int NC>
__global__ void __launch_bounds__(256, 1)
gemm_mma_body(const float* __restrict__ A,
              const float* __restrict__ W,
              float* __restrict__ C) {
    constexpr int SA = 132;          // A row stride (floats)
    constexpr int SB = NC + 8;       // B row stride (floats)
    constexpr int WN = NC / 2;       // warp n-extent
    constexpr int NT = WN / 8;       // n-tiles per warp
    extern __shared__ float sm[];
    float* As = sm;                  // [128][SA]
    float* Bs = sm + 128 * SA;       // [128][SB]

    int tid = threadIdx.x;
    int wid = tid >> 5;
    int lane = tid & 31;
    int m0 = blockIdx.x * 128;
    int wm = (wid & 3) * 32;
    int wn = (wid >> 2) * WN;
    int r = lane >> 2;               // fragment group id
    int cq = lane & 3;               // thread-in-group

    // fill A (128 x 32 float4), convert to tf32
    const float4* A4 = (const float4*)A;
#pragma unroll
    for (int it = 0; it < 16; it++) {
        int idx = it * 256 + tid;
        int rr = idx >> 5, c4 = idx & 31;
        float4 v = make_float4(0.f, 0.f, 0.f, 0.f);
        int gr = m0 + rr;
        if (gr < NN) v = A4[gr * 32 + c4];
        uint32_t* dst = (uint32_t*)&As[rr * SA + c4 * 4];
        dst[0] = f2tf32(v.x); dst[1] = f2tf32(v.y);
        dst[2] = f2tf32(v.z); dst[3] = f2tf32(v.w);
    }
    // fill B (128 x NC/4 float4), convert to tf32
    const float4* W4 = (const float4*)W;
#pragma unroll
    for (int it = 0; it < (128 * NC / 4) / 256; it++) {
        int idx = it * 256 + tid;
        int kk = idx / (NC / 4), c4 = idx % (NC / 4);
        float4 v = W4[idx];
        uint32_t* dst = (uint32_t*)&Bs[kk * SB + c4 * 4];
        dst[0] = f2tf32(v.x); dst[1] = f2tf32(v.y);
        dst[2] = f2tf32(v.z); dst[3] = f2tf32(v.w);
    }
    __syncthreads();

    float acc[2][NT][4];
#pragma unroll
    for (int im = 0; im < 2; im++)
#pragma unroll
        for (int in = 0; in < NT; in++)
#pragma unroll
            for (int q = 0; q < 4; q++) acc[im][in][q] = 0.f;

    const uint32_t* Au = (const uint32_t*)As;
    const uint32_t* Bu = (const uint32_t*)Bs;

#pragma unroll
    for (int ks = 0; ks < 16; ks++) {
        int k0 = ks * 8;
        uint32_t a[2][4];
#pragma unroll
        for (int im = 0; im < 2; im++) {
            int base = wm + im * 16;
            a[im][0] = Au[(base + r) * SA + k0 + cq];
            a[im][1] = Au[(base + r + 8) * SA + k0 + cq];
            a[im][2] = Au[(base + r) * SA + k0 + cq + 4];
            a[im][3] = Au[(base + r + 8) * SA + k0 + cq + 4];
        }
#pragma unroll
        for (int in = 0; in < NT; in++) {
            int col = wn + in * 8 + r;
            uint32_t b0 = Bu[(k0 + cq) * SB + col];
            uint32_t b1 = Bu[(k0 + cq + 4) * SB + col];
#pragma unroll
            for (int im = 0; im < 2; im++)
                mma_tf32(acc[im][in][0], acc[im][in][1], acc[im][in][2], acc[im][in][3],
                         a[im][0], a[im][1], a[im][2], a[im][3], b0, b1);
        }
    }

    // epilogue: c0,c1 at (row, 2cq..+1); c2,c3 at (row+8, ...)
#pragma unroll
    for (int im = 0; im < 2; im++) {
        int row = m0 + wm + im * 16 + r;
#pragma unroll
        for (int in = 0; in < NT; in++) {
            int col = wn + in * 8 + 2 * cq;
            if (row < NN)
                *(float2*)&C[row * NC + col] = make_float2(acc[im][in][0], acc[im][in][1]);
            if (row + 8 < NN)
                *(float2*)&C[(row + 8) * NC + col] = make_float2(acc[im][in][2], acc[im][in][3]);
        }
    }
}

// wrappers binding device-global scratch
__global__ void __launch_bounds__(256, 1)
gemm0_mma(const float* __restrict__ x, const float* __restrict__ W0) {
    constexpr int NC = HIDF;
    constexpr int SA = 132, SB = NC + 8, WN = NC / 2, NT = WN / 8;
    extern __shared__ float sm[];
    float* As = sm; float* Bs = sm + 128 * SA;
    const float* A = x; const float* W = W0; float* C = (float*)g_support0;
    int tid = threadIdx.x, wid = tid >> 5, lane = tid & 31;
    int m0 = blockIdx.x * 128;
    int wm = (wid & 3) * 32, wn = (wid >> 2) * WN;
    int r = lane >> 2, cq = lane & 3;
    const float4* A4 = (const float4*)A;
#pragma unroll
    for (int it = 0; it < 16; it++) {
        int idx = it * 256 + tid;
        int rr = idx >> 5, c4 = idx & 31;
        float4 v = make_float4(0.f, 0.f, 0.f, 0.f);
        int gr = m0 + rr;
        if (gr < NN) v = A4[gr * 32 + c4];
        uint32_t* dst = (uint32_t*)&As[rr * SA + c4 * 4];
        dst[0] = f2tf32(v.x); dst[1] = f2tf32(v.y);
        dst[2] = f2tf32(v.z); dst[3] = f2tf32(v.w);
    }
    const float4* W4 = (const float4*)W;
#pragma unroll
    for (int it = 0; it < (128 * NC / 4) / 256; it++) {
        int idx = it * 256 + tid;
        int kk = idx / (NC / 4), c4 = idx % (NC / 4);
        float4 v = W4[idx];
        uint32_t* dst = (uint32_t*)&Bs[kk * SB + c4 * 4];
        dst[0] = f2tf32(v.x); dst[1] = f2tf32(v.y);
        dst[2] = f2tf32(v.z); dst[3] = f2tf32(v.w);
    }
    __syncthreads();
    float acc[2][NT][4];
#pragma unroll
    for (int im = 0; im < 2; im++)
#pragma unroll
        for (int in = 0; in < NT; in++)
#pragma unroll
            for (int q = 0; q < 4; q++) acc[im][in][q] = 0.f;
    const uint32_t* Au = (const uint32_t*)As;
    const uint32_t* Bu = (const uint32_t*)Bs;
#pragma unroll
    for (int ks = 0; ks < 16; ks++) {
        int k0 = ks * 8;
        uint32_t a[2][4];
#pragma unroll
        for (int im = 0; im < 2; im++) {
            int base = wm + im * 16;
            a[im][0] = Au[(base + r) * SA + k0 + cq];
            a[im][1] = Au[(base + r + 8) * SA + k0 + cq];
            a[im][2] = Au[(base + r) * SA + k0 + cq + 4];
            a[im][3] = Au[(base + r + 8) * SA + k0 + cq + 4];
        }
#pragma unroll
        for (int in = 0; in < NT; in++) {
            int col = wn + in * 8 + r;
            uint32_t b0 = Bu[(k0 + cq) * SB + col];
            uint32_t b1 = Bu[(k0 + cq + 4) * SB + col];
#pragma unroll
            for (int im = 0; im < 2; im++)
                mma_tf32(acc[im][in][0], acc[im][in][1], acc[im][in][2], acc[im][in][3],
                         a[im][0], a[im][1], a[im][2], a[im][3], b0, b1);
        }
    }
#pragma unroll
    for (int im = 0; im < 2; im++) {
        int row = m0 + wm + im * 16 + r;
#pragma unroll
        for (int in = 0; in < NT; in++) {
            int col = wn + in * 8 + 2 * cq;
            if (row < NN)
                *(float2*)&C[row * NC + col] = make_float2(acc[im][in][0], acc[im][in][1]);
            if (row + 8 < NN)
                *(float2*)&C[(row + 8) * NC + col] = make_float2(acc[im][in][2], acc[im][in][3]);
        }
    }
}

__global__ void __launch_bounds__(256, 1)
gemm1_mma(const float* __restrict__ W1) {
    constexpr int NC = OUTF;
    constexpr int SA = 132, SB = NC + 8, WN = NC / 2, NT = WN / 8;
    extern __shared__ float sm[];
    float* As = sm; float* Bs = sm + 128 * SA;
    const float* A = (const float*)g_h; const float* W = W1;
    float* C = (float*)g_support1;
    int tid = threadIdx.x, wid = tid >> 5, lane = tid & 31;
    int m0 = blockIdx.x * 128;
    int wm = (wid & 3) * 32, wn = (wid >> 2) * WN;
    int r = lane >> 2, cq = lane & 3;
    const float4* A4 = (const float4*)A;
#pragma unroll
    for (int it = 0; it < 16; it++) {
        int idx = it * 256 + tid;
        int rr = idx >> 5, c4 = idx & 31;
        float4 v = make_float4(0.f, 0.f, 0.f, 0.f);
        int gr = m0 + rr;
        if (gr < NN) v = A4[gr * 32 + c4];
        uint32_t* dst = (uint32_t*)&As[rr * SA + c4 * 4];
        dst[0] = f2tf32(v.x); dst[1] = f2tf32(v.y);
        dst[2] = f2tf32(v.z); dst[3] = f2tf32(v.w);
    }
    const float4* W4 = (const float4*)W;
#pragma unroll
    for (int it = 0; it < (128 * NC / 4) / 256; it++) {
        int idx = it * 256 + tid;
        int kk = idx / (NC / 4), c4 = idx % (NC / 4);
        float4 v = W4[idx];
        uint32_t* dst = (uint32_t*)&Bs[kk * SB + c4 * 4];
        dst[0] = f2tf32(v.x); dst[1] = f2tf32(v.y);
        dst[2] = f2tf32(v.z); dst[3] = f2tf32(v.w);
    }
    __syncthreads();
    float acc[2][NT][4];
#pragma unroll
    for (int im = 0; im < 2; im++)
#pragma unroll
        for (int in = 0; in < NT; in++)
#pragma unroll
            for (int q = 0; q < 4; q++) acc[im][in][q] = 0.f;
    const uint32_t* Au = (const uint32_t*)As;
    const uint32_t* Bu = (const uint32_t*)Bs;
#pragma unroll
    for (int ks = 0; ks < 16; ks++) {
        int k0 = ks * 8;
        uint32_t a[2][4];
#pragma unroll
        for (int im = 0; im < 2; im++) {
            int base = wm + im * 16;
            a[im][0] = Au[(base + r) * SA + k0 + cq];
            a[im][1] = Au[(base + r + 8) * SA + k0 + cq];
            a[im][2] = Au[(base + r) * SA + k0 + cq + 4];
            a[im][3] = Au[(base + r + 8) * SA + k0 + cq + 4];
        }
#pragma unroll
        for (int in = 0; in < NT; in++) {
            int col = wn + in * 8 + r;
            uint32_t b0 = Bu[(k0 + cq) * SB + col];
            uint32_t b1 = Bu[(k0 + cq + 4) * SB + col];
#pragma unroll
            for (int im = 0; im < 2; im++)
                mma_tf32(acc[im][in][0], acc[im][in][1], acc[im][in][2], acc[im][in][3],
                         a[im][0], a[im][1], a[im][2], a[im][3], b0, b1);
        }
    }
#pragma unroll
    for (int im = 0; im < 2; im++) {
        int row = m0 + wm + im * 16 + r;
#pragma unroll
        for (int in = 0; in < NT; in++) {
            int col = wn + in * 8 + 2 * cq;
            if (row < NN)
                *(float2*)&C[row * NC + col] = make_float2(acc[im][in][0], acc[im][in][1]);
            if (row + 8 < NN)
                *(float2*)&C[(row + 8) * NC + col] = make_float2(acc[im][in][2], acc[im][in][3]);
        }
    }
}

// ---------------- scan phase 1: block-local exclusive scan -----------------
__global__ void scan_phase1_kernel() {
    __shared__ int s[SCAN_BLK];
    int which = blockIdx.y;
    const int* __restrict__ cnt = which ? g_cnt1 : g_cnt0;
    int* __restrict__ ptr = which ? g_ptr1 : g_ptr0;
    int tid = threadIdx.x;
    int i = blockIdx.x * SCAN_BLK + tid;
    int v = (i < NN) ? cnt[i] : 0;
    s[tid] = v;
    __syncthreads();
#pragma unroll
    for (int off = 1; off < SCAN_BLK; off <<= 1) {
        int t = (tid >= off) ? s[tid - off] : 0;
        __syncthreads();
        s[tid] += t;
        __syncthreads();
    }
    if (i < NN) ptr[i] = s[tid] - v;
    if (tid == SCAN_BLK - 1) g_bsum[which][blockIdx.x] = s[tid];
}

// ---------------- scan phase 2: scan the block sums ------------------------
__global__ void scan_phase2_kernel() {
    __shared__ int s[128];
    int tid = threadIdx.x;
    for (int which = 0; which < 2; which++) {
        int v = (tid < NBLK) ? g_bsum[which][tid] : 0;
        s[tid] = v;
        __syncthreads();
#pragma unroll
        for (int off = 1; off < 128; off <<= 1) {
            int t = (tid >= off) ? s[tid - off] : 0;
            __syncthreads();
            s[tid] += t;
            __syncthreads();
        }
        if (tid < NBLK) g_boff[which][tid] = s[tid] - v;
        if (tid == NBLK - 1) {
            if (which) g_ptr1[NN] = s[tid];
            else       g_ptr0[NN] = s[tid];
        }
        __syncthreads();
    }
}

// ---------------- scan phase 3: add block offsets, init cursors ------------
__global__ void scan_phase3_kernel() {
    int which = blockIdx.y;
    int* __restrict__ ptr = which ? g_ptr1 : g_ptr0;
    int* __restrict__ cur = which ? g_cur1 : g_cur0;
    int i = blockIdx.x * SCAN_BLK + threadIdx.x;
    if (i < NN) {
        int v = ptr[i] + g_boff[which][blockIdx.x];
        ptr[i] = v;
        cur[i] = v;
    }
}

// ---------------- counting-sort scatter of (col,val) by row ----------------
__global__ void scatter_kernel(const int* __restrict__ row,
                               const int* __restrict__ col,
                               const float* __restrict__ val,
                               int which) {
    int* __restrict__ cur  = which ? g_cur1  : g_cur0;
    int* __restrict__ scol = which ? g_scol1 : g_scol0;
    float* __restrict__ sval = which ? g_sval1 : g_sval0;
    int i = blockIdx.x * blockDim.x + threadIdx.x;
    if (i < EE) {
        int r = row[i];
        int p = atomicAdd(&cur[r], 1);
        scol[p] = col[i];
        sval[p] = val[i];
    }
}

// ---------------- CSR row-gather SpMM, F=128 (float4/lane), bias+relu ------
__global__ void spmm128_kernel(const float* __restrict__ bias) {
    int gtid = blockIdx.x * blockDim.x + threadIdx.x;
    int r = gtid >> 5;
    int lane = gtid & 31;
    if (r >= NN) return;
    int s = g_ptr0[r], e = g_ptr0[r + 1];
    float4 acc = make_float4(0.f, 0.f, 0.f, 0.f);
    for (int i = s; i < e; i++) {
        int c = __ldg(&g_scol0[i]);
        float v = __ldg(&g_sval0[i]);
        float4 t = __ldg(&g_support0[c * 32 + lane]);
        acc.x += v * t.x; acc.y += v * t.y;
        acc.z += v * t.z; acc.w += v * t.w;
    }
    float4 b = ((const float4*)bias)[lane];
    acc.x += b.x; acc.y += b.y; acc.z += b.z; acc.w += b.w;
    acc.x = fmaxf(acc.x, 0.f); acc.y = fmaxf(acc.y, 0.f);
    acc.z = fmaxf(acc.z, 0.f); acc.w = fmaxf(acc.w, 0.f);
    g_h[r * 32 + lane] = acc;
}

// ---------------- CSR row-gather SpMM, F=64 (float2/lane), bias ------------
__global__ void spmm64_kernel(const float* __restrict__ bias,
                              float2* __restrict__ out2) {
    int gtid = blockIdx.x * blockDim.x + threadIdx.x;
    int r = gtid >> 5;
    int lane = gtid & 31;
    if (r >= NN) return;
    int s = g_ptr1[r], e = g_ptr1[r + 1];
    const float2* __restrict__ S2 = (const float2*)g_support1;
    float2 acc = make_float2(0.f, 0.f);
    for (int i = s; i < e; i++) {
        int c = __ldg(&g_scol1[i]);
        float v = __ldg(&g_sval1[i]);
        float2 t = __ldg(&S2[c * 32 + lane]);
        acc.x += v * t.x; acc.y += v * t.y;
    }
    float2 b = ((const float2*)bias)[lane];
    acc.x += b.x; acc.y += b.y;
    out2[r * 32 + lane] = acc;
}

// ---------------- launch ---------------------------------------------------
extern "C" void kernel_launch(void* const* d_in, const int* in_sizes, int n_in,
                              void* d_out, int out_size) {
    const float* x    = (const float*)d_in[0];
    const int*   row0 = (const int*)d_in[1];
    const int*   col0 = (const int*)d_in[2];
    const float* val0 = (const float*)d_in[3];
    const int*   row1 = (const int*)d_in[4];
    const int*   col1 = (const int*)d_in[5];
    const float* val1 = (const float*)d_in[6];
    const float* W0   = (const float*)d_in[7];
    const float* b0   = (const float*)d_in[8];
    const float* W1   = (const float*)d_in[9];
    const float* b1   = (const float*)d_in[10];
    float* out = (float*)d_out;

    const int TB = 256;
    // smem: A 128*132*4 = 67584 ; B0 128*136*4 = 69632 ; B1 128*72*4 = 36864
    const int SMEM_G0 = 128 * 132 * 4 + 128 * (HIDF + 8) * 4;  // 137216
    const int SMEM_G1 = 128 * 132 * 4 + 128 * (OUTF + 8) * 4;  // 104448
    cudaFuncSetAttribute(gemm0_mma, cudaFuncAttributeMaxDynamicSharedMemorySize, SMEM_G0);
    cudaFuncSetAttribute(gemm1_mma, cudaFuncAttributeMaxDynamicSharedMemorySize, SMEM_G1);

    // 1) zero counters
    zero_counts_kernel<<<(NN + TB - 1) / TB, TB>>>();

    // 2) histograms (both layers)
    hist_kernel<<<(EE + TB - 1) / TB, TB>>>(row0, row1);

    // 3) support0 = x @ W0 (tf32 mma.sync)
    gemm0_mma<<<(NN + 127) / 128, 256, SMEM_G0>>>(x, W0);

    // 4) multi-block exclusive scans
    {
        dim3 g1(NBLK, 2);
        scan_phase1_kernel<<<g1, SCAN_BLK>>>();
        scan_phase2_kernel<<<1, 128>>>();
        scan_phase3_kernel<<<g1, SCAN_BLK>>>();
    }

    // 5) counting-sort scatter
    scatter_kernel<<<(EE + TB - 1) / TB, TB>>>(row0, col0, val0, 0);
    scatter_kernel<<<(EE + TB - 1) / TB, TB>>>(row1, col1, val1, 1);

    // 6) h = relu(spmm(adj0, support0) + b0)
    spmm128_kernel<<<(NN * 32 + TB - 1) / TB, TB>>>(b0);

    // 7) support1 = h @ W1 (tf32 mma.sync)
    gemm1_mma<<<(NN + 127) / 128, 256, SMEM_G1>>>(W1);

    // 8) out = spmm(adj1, support1) + b1
    spmm64_kernel<<<(NN * 32 + TB - 1) / TB, TB>>>(b1, (float2*)out);
}

// round 6
// speedup vs baseline: 2.7395x; 1.1255x over previous
#include <cuda_runtime.h>
#include <cuda_fp16.h>
#include <cstdint>

#define NN 50000
#define EE 800000
#define INF 128
#define HIDF 128
#define OUTF 64

#define SCAN_BLK 512
#define NBLK ((NN + SCAN_BLK - 1) / SCAN_BLK)   // 98

// ---------------- scratch (__device__ globals; no allocation allowed) ------
__device__ uint2  g_sup0h[NN * 32];   // fp16 support0 [NN][128]
__device__ uint2  g_hh[NN * 32];      // fp16 h        [NN][128]
__device__ uint32_t g_sup1h[NN * 32]; // fp16 support1 [NN][64]
__device__ int    g_cnt0[NN];
__device__ int    g_cnt1[NN];
__device__ int    g_ptr0[NN + 1];
__device__ int    g_ptr1[NN + 1];
__device__ int    g_cur0[NN];
__device__ int    g_cur1[NN];
__device__ int    g_bsum[2][NBLK];
__device__ int    g_boff[2][NBLK];
__device__ int    g_scol0[EE];
__device__ float  g_sval0[EE];
__device__ int    g_scol1[EE];
__device__ float  g_sval1[EE];

// ---------------- small helpers -------------------------------------------
__device__ __forceinline__ uint32_t f2tf32(float f) {
    uint32_t r;
    asm("cvt.rna.tf32.f32 %0, %1;" : "=r"(r) : "f"(f));
    return r;
}
__device__ __forceinline__ void mma_tf32(float& c0, float& c1, float& c2, float& c3,
                                         uint32_t a0, uint32_t a1, uint32_t a2, uint32_t a3,
                                         uint32_t b0, uint32_t b1) {
    asm volatile(
        "mma.sync.aligned.m16n8k8.row.col.f32.tf32.tf32.f32 "
        "{%0,%1,%2,%3}, {%4,%5,%6,%7}, {%8,%9}, {%0,%1,%2,%3};"
        : "+f"(c0), "+f"(c1), "+f"(c2), "+f"(c3)
        : "r"(a0), "r"(a1), "r"(a2), "r"(a3), "r"(b0), "r"(b1));
}

// ---------------- zero counters -------------------------------------------
__global__ void zero_counts_kernel() {
    int i = blockIdx.x * blockDim.x + threadIdx.x;
    if (i < NN) { g_cnt0[i] = 0; g_cnt1[i] = 0; }
}

// ---------------- histogram of row indices (int4 vectorized) ---------------
__global__ void hist_kernel(const int* __restrict__ row0,
                            const int* __restrict__ row1) {
    int i = blockIdx.x * blockDim.x + threadIdx.x;
    if (i < EE / 4) {
        int4 r0 = ((const int4*)row0)[i];
        atomicAdd(&g_cnt0[r0.x], 1); atomicAdd(&g_cnt0[r0.y], 1);
        atomicAdd(&g_cnt0[r0.z], 1); atomicAdd(&g_cnt0[r0.w], 1);
        int4 r1 = ((const int4*)row1)[i];
        atomicAdd(&g_cnt1[r1.x], 1); atomicAdd(&g_cnt1[r1.y], 1);
        atomicAdd(&g_cnt1[r1.z], 1); atomicAdd(&g_cnt1[r1.w], 1);
    }
}

// ---------------- scan phase 1: block-local exclusive scan -----------------
__global__ void scan_phase1_kernel() {
    __shared__ int s[SCAN_BLK];
    int which = blockIdx.y;
    const int* __restrict__ cnt = which ? g_cnt1 : g_cnt0;
    int* __restrict__ ptr = which ? g_ptr1 : g_ptr0;
    int tid = threadIdx.x;
    int i = blockIdx.x * SCAN_BLK + tid;
    int v = (i < NN) ? cnt[i] : 0;
    s[tid] = v;
    __syncthreads();
#pragma unroll
    for (int off = 1; off < SCAN_BLK; off <<= 1) {
        int t = (tid >= off) ? s[tid - off] : 0;
        __syncthreads();
        s[tid] += t;
        __syncthreads();
    }
    if (i < NN) ptr[i] = s[tid] - v;
    if (tid == SCAN_BLK - 1) g_bsum[which][blockIdx.x] = s[tid];
}

// ---------------- scan phase 2: scan the block sums ------------------------
__global__ void scan_phase2_kernel() {
    __shared__ int s[128];
    int tid = threadIdx.x;
    for (int which = 0; which < 2; which++) {
        int v = (tid < NBLK) ? g_bsum[which][tid] : 0;
        s[tid] = v;
        __syncthreads();
#pragma unroll
        for (int off = 1; off < 128; off <<= 1) {
            int t = (tid >= off) ? s[tid - off] : 0;
            __syncthreads();
            s[tid] += t;
            __syncthreads();
        }
        if (tid < NBLK) g_boff[which][tid] = s[tid] - v;
        if (tid == NBLK - 1) {
            if (which) g_ptr1[NN] = s[tid];
            else       g_ptr0[NN] = s[tid];
        }
        __syncthreads();
    }
}

// ---------------- scan phase 3: add block offsets, init cursors ------------
__global__ void scan_phase3_kernel() {
    int which = blockIdx.y;
    int* __restrict__ ptr = which ? g_ptr1 : g_ptr0;
    int* __restrict__ cur = which ? g_cur1 : g_cur0;
    int i = blockIdx.x * SCAN_BLK + threadIdx.x;
    if (i < NN) {
        int v = ptr[i] + g_boff[which][blockIdx.x];
        ptr[i] = v;
        cur[i] = v;
    }
}

// ---------------- counting-sort scatter (both layers, vectorized) ----------
__global__ void scatter_kernel(const int* __restrict__ row0,
                               const int* __restrict__ col0,
                               const float* __restrict__ val0,
                               const int* __restrict__ row1,
                               const int* __restrict__ col1,
                               const float* __restrict__ val1) {
    int which = blockIdx.y;
    const int* __restrict__ row   = which ? row1 : row0;
    const int* __restrict__ col   = which ? col1 : col0;
    const float* __restrict__ val = which ? val1 : val0;
    int* __restrict__ cur  = which ? g_cur1  : g_cur0;
    int* __restrict__ scol = which ? g_scol1 : g_scol0;
    float* __restrict__ sval = which ? g_sval1 : g_sval0;
    int i = blockIdx.x * blockDim.x + threadIdx.x;
    if (i < EE / 4) {
        int4 r = ((const int4*)row)[i];
        int4 c = ((const int4*)col)[i];
        float4 v = ((const float4*)val)[i];
        int p;
        p = atomicAdd(&cur[r.x], 1); scol[p] = c.x; sval[p] = v.x;
        p = atomicAdd(&cur[r.y], 1); scol[p] = c.y; sval[p] = v.y;
        p = atomicAdd(&cur[r.z], 1); scol[p] = c.z; sval[p] = v.z;
        p = atomicAdd(&cur[r.w], 1); scol[p] = c.w; sval[p] = v.w;
    }
}

// ---------------- GEMM 0: support0h = fp16( x @ W0 ), tf32 mma.sync --------
// CTA: 128 rows x 128 cols, K=128 resident. 256 threads = 8 warps (4m x 2n).
__global__ void __launch_bounds__(256, 1)
gemm0_mma(const float* __restrict__ x, const float* __restrict__ W0) {
    constexpr int NC = HIDF;
    constexpr int SA = 132, SB = NC + 8, WN = NC / 2, NT = WN / 8;
    extern __shared__ float sm[];
    float* As = sm; float* Bs = sm + 128 * SA;
    int tid = threadIdx.x, wid = tid >> 5, lane = tid & 31;
    int m0 = blockIdx.x * 128;
    int wm = (wid & 3) * 32, wn = (wid >> 2) * WN;
    int r = lane >> 2, cq = lane & 3;
    const float4* A4 = (const float4*)x;
#pragma unroll
    for (int it = 0; it < 16; it++) {
        int idx = it * 256 + tid;
        int rr = idx >> 5, c4 = idx & 31;
        float4 v = make_float4(0.f, 0.f, 0.f, 0.f);
        int gr = m0 + rr;
        if (gr < NN) v = A4[gr * 32 + c4];
        uint32_t* dst = (uint32_t*)&As[rr * SA + c4 * 4];
        dst[0] = f2tf32(v.x); dst[1] = f2tf32(v.y);
        dst[2] = f2tf32(v.z); dst[3] = f2tf32(v.w);
    }
    const float4* W4 = (const float4*)W0;
#pragma unroll
    for (int it = 0; it < (128 * NC / 4) / 256; it++) {
        int idx = it * 256 + tid;
        int kk = idx / (NC / 4), c4 = idx % (NC / 4);
        float4 v = W4[idx];
        uint32_t* dst = (uint32_t*)&Bs[kk * SB + c4 * 4];
        dst[0] = f2tf32(v.x); dst[1] = f2tf32(v.y);
        dst[2] = f2tf32(v.z); dst[3] = f2tf32(v.w);
    }
    __syncthreads();
    float acc[2][NT][4];
#pragma unroll
    for (int im = 0; im < 2; im++)
#pragma unroll
        for (int in = 0; in < NT; in++)
#pragma unroll
            for (int q = 0; q < 4; q++) acc[im][in][q] = 0.f;
    const uint32_t* Au = (const uint32_t*)As;
    const uint32_t* Bu = (const uint32_t*)Bs;
#pragma unroll
    for (int ks = 0; ks < 16; ks++) {
        int k0 = ks * 8;
        uint32_t a[2][4];
#pragma unroll
        for (int im = 0; im < 2; im++) {
            int base = wm + im * 16;
            a[im][0] = Au[(base + r) * SA + k0 + cq];
            a[im][1] = Au[(base + r + 8) * SA + k0 + cq];
            a[im][2] = Au[(base + r) * SA + k0 + cq + 4];
            a[im][3] = Au[(base + r + 8) * SA + k0 + cq + 4];
        }
#pragma unroll
        for (int in = 0; in < NT; in++) {
            int colx = wn + in * 8 + r;
            uint32_t b0 = Bu[(k0 + cq) * SB + colx];
            uint32_t b1 = Bu[(k0 + cq + 4) * SB + colx];
#pragma unroll
            for (int im = 0; im < 2; im++)
                mma_tf32(acc[im][in][0], acc[im][in][1], acc[im][in][2], acc[im][in][3],
                         a[im][0], a[im][1], a[im][2], a[im][3], b0, b1);
        }
    }
    __half2* C2 = (__half2*)g_sup0h;     // [NN][64] half2
#pragma unroll
    for (int im = 0; im < 2; im++) {
        int row = m0 + wm + im * 16 + r;
#pragma unroll
        for (int in = 0; in < NT; in++) {
            int colh = (wn + in * 8 + 2 * cq) >> 1;  // half2 index
            if (row < NN)
                C2[row * 64 + colh] = __floats2half2_rn(acc[im][in][0], acc[im][in][1]);
            if (row + 8 < NN)
                C2[(row + 8) * 64 + colh] = __floats2half2_rn(acc[im][in][2], acc[im][in][3]);
        }
    }
}

// ---------------- GEMM 1: support1h = fp16( h @ W1 ), tf32 mma.sync --------
__global__ void __launch_bounds__(256, 1)
gemm1_mma(const float* __restrict__ W1) {
    constexpr int NC = OUTF;
    constexpr int SA = 132, SB = NC + 8, WN = NC / 2, NT = WN / 8;
    extern __shared__ float sm[];
    float* As = sm; float* Bs = sm + 128 * SA;
    int tid = threadIdx.x, wid = tid >> 5, lane = tid & 31;
    int m0 = blockIdx.x * 128;
    int wm = (wid & 3) * 32, wn = (wid >> 2) * WN;
    int r = lane >> 2, cq = lane & 3;
    // A fill from fp16 h (exact fp16 -> tf32)
#pragma unroll
    for (int it = 0; it < 16; it++) {
        int idx = it * 256 + tid;
        int rr = idx >> 5, c = idx & 31;     // c indexes uint2 (4 features)
        uint2 t = make_uint2(0u, 0u);
        int gr = m0 + rr;
        if (gr < NN) t = g_hh[gr * 32 + c];
        float2 f0 = __half22float2(*(__half2*)&t.x);
        float2 f1 = __half22float2(*(__half2*)&t.y);
        uint32_t* dst = (uint32_t*)&As[rr * SA + c * 4];
        dst[0] = f2tf32(f0.x); dst[1] = f2tf32(f0.y);
        dst[2] = f2tf32(f1.x); dst[3] = f2tf32(f1.y);
    }
    const float4* W4 = (const float4*)W1;
#pragma unroll
    for (int it = 0; it < (128 * NC / 4) / 256; it++) {
        int idx = it * 256 + tid;
        int kk = idx / (NC / 4), c4 = idx % (NC / 4);
        float4 v = W4[idx];
        uint32_t* dst = (uint32_t*)&Bs[kk * SB + c4 * 4];
        dst[0] = f2tf32(v.x); dst[1] = f2tf32(v.y);
        dst[2] = f2tf32(v.z); dst[3] = f2tf32(v.w);
    }
    __syncthreads();
    float acc[2][NT][4];
#pragma unroll
    for (int im = 0; im < 2; im++)
#pragma unroll
        for (int in = 0; in < NT; in++)
#pragma unroll
            for (int q = 0; q < 4; q++) acc[im][in][q] = 0.f;
    const uint32_t* Au = (const uint32_t*)As;
    const uint32_t* Bu = (const uint32_t*)Bs;
#pragma unroll
    for (int ks = 0; ks < 16; ks++) {
        int k0 = ks * 8;
        uint32_t a[2][4];
#pragma unroll
        for (int im = 0; im < 2; im++) {
            int base = wm + im * 16;
            a[im][0] = Au[(base + r) * SA + k0 + cq];
            a[im][1] = Au[(base + r + 8) * SA + k0 + cq];
            a[im][2] = Au[(base + r) * SA + k0 + cq + 4];
            a[im][3] = Au[(base + r + 8) * SA + k0 + cq + 4];
        }
#pragma unroll
        for (int in = 0; in < NT; in++) {
            int colx = wn + in * 8 + r;
            uint32_t b0 = Bu[(k0 + cq) * SB + colx];
            uint32_t b1 = Bu[(k0 + cq + 4) * SB + colx];
#pragma unroll
            for (int im = 0; im < 2; im++)
                mma_tf32(acc[im][in][0], acc[im][in][1], acc[im][in][2], acc[im][in][3],
                         a[im][0], a[im][1], a[im][2], a[im][3], b0, b1);
        }
    }
    __half2* C2 = (__half2*)g_sup1h;     // [NN][32] half2
#pragma unroll
    for (int im = 0; im < 2; im++) {
        int row = m0 + wm + im * 16 + r;
#pragma unroll
        for (int in = 0; in < NT; in++) {
            int colh = (wn + in * 8 + 2 * cq) >> 1;
            if (row < NN)
                C2[row * 32 + colh] = __floats2half2_rn(acc[im][in][0], acc[im][in][1]);
            if (row + 8 < NN)
                C2[(row + 8) * 32 + colh] = __floats2half2_rn(acc[im][in][2], acc[im][in][3]);
        }
    }
}

// ---------------- CSR row-gather SpMM, F=128 fp16 in, fp16 out -------------
// warp/row; lane loads uint2 = 4 fp16 features; fp32 accum; bias+relu.
__global__ void spmm128_kernel(const float* __restrict__ bias) {
    int gtid = blockIdx.x * blockDim.x + threadIdx.x;
    int r = gtid >> 5;
    int lane = gtid & 31;
    if (r >= NN) return;
    int s = g_ptr0[r], e = g_ptr0[r + 1];
    float a0 = 0.f, a1 = 0.f, a2 = 0.f, a3 = 0.f;
    for (int i = s; i < e; i++) {
        int c = __ldg(&g_scol0[i]);
        float v = __ldg(&g_sval0[i]);
        uint2 t = __ldg(&g_sup0h[c * 32 + lane]);
        float2 f0 = __half22float2(*(__half2*)&t.x);
        float2 f1 = __half22float2(*(__half2*)&t.y);
        a0 += v * f0.x; a1 += v * f0.y; a2 += v * f1.x; a3 += v * f1.y;
    }
    float4 b = ((const float4*)bias)[lane];
    a0 = fmaxf(a0 + b.x, 0.f); a1 = fmaxf(a1 + b.y, 0.f);
    a2 = fmaxf(a2 + b.z, 0.f); a3 = fmaxf(a3 + b.w, 0.f);
    uint2 o;
    *(__half2*)&o.x = __floats2half2_rn(a0, a1);
    *(__half2*)&o.y = __floats2half2_rn(a2, a3);
    g_hh[r * 32 + lane] = o;
}

// ---------------- CSR row-gather SpMM, F=64 fp16 in, fp32 out --------------
__global__ void spmm64_kernel(const float* __restrict__ bias,
                              float2* __restrict__ out2) {
    int gtid = blockIdx.x * blockDim.x + threadIdx.x;
    int r = gtid >> 5;
    int lane = gtid & 31;
    if (r >= NN) return;
    int s = g_ptr1[r], e = g_ptr1[r + 1];
    float a0 = 0.f, a1 = 0.f;
    for (int i = s; i < e; i++) {
        int c = __ldg(&g_scol1[i]);
        float v = __ldg(&g_sval1[i]);
        uint32_t t = __ldg(&g_sup1h[c * 32 + lane]);
        float2 f = __half22float2(*(__half2*)&t);
        a0 += v * f.x; a1 += v * f.y;
    }
    float2 b = ((const float2*)bias)[lane];
    out2[r * 32 + lane] = make_float2(a0 + b.x, a1 + b.y);
}

// ---------------- launch ---------------------------------------------------
extern "C" void kernel_launch(void* const* d_in, const int* in_sizes, int n_in,
                              void* d_out, int out_size) {
    const float* x    = (const float*)d_in[0];
    const int*   row0 = (const int*)d_in[1];
    const int*   col0 = (const int*)d_in[2];
    const float* val0 = (const float*)d_in[3];
    const int*   row1 = (const int*)d_in[4];
    const int*   col1 = (const int*)d_in[5];
    const float* val1 = (const float*)d_in[6];
    const float* W0   = (const float*)d_in[7];
    const float* b0   = (const float*)d_in[8];
    const float* W1   = (const float*)d_in[9];
    const float* b1   = (const float*)d_in[10];
    float* out = (float*)d_out;

    const int TB = 256;
    const int SMEM_G0 = 128 * 132 * 4 + 128 * (HIDF + 8) * 4;  // 137216
    const int SMEM_G1 = 128 * 132 * 4 + 128 * (OUTF + 8) * 4;  // 104448
    cudaFuncSetAttribute(gemm0_mma, cudaFuncAttributeMaxDynamicSharedMemorySize, SMEM_G0);
    cudaFuncSetAttribute(gemm1_mma, cudaFuncAttributeMaxDynamicSharedMemorySize, SMEM_G1);

    // 1) zero counters
    zero_counts_kernel<<<(NN + TB - 1) / TB, TB>>>();

    // 2) histograms (both layers, int4)
    hist_kernel<<<(EE / 4 + TB - 1) / TB, TB>>>(row0, row1);

    // 3) support0 = fp16(x @ W0)  (tf32 mma.sync)
    gemm0_mma<<<(NN + 127) / 128, 256, SMEM_G0>>>(x, W0);

    // 4) multi-block exclusive scans
    {
        dim3 g1(NBLK, 2);
        scan_phase1_kernel<<<g1, SCAN_BLK>>>();
        scan_phase2_kernel<<<1, 128>>>();
        scan_phase3_kernel<<<g1, SCAN_BLK>>>();
    }

    // 5) counting-sort scatter, both layers in one launch
    {
        dim3 gs((EE / 4 + TB - 1) / TB, 2);
        scatter_kernel<<<gs, TB>>>(row0, col0, val0, row1, col1, val1);
    }

    // 6) h = fp16(relu(spmm(adj0, support0) + b0))
    spmm128_kernel<<<(NN * 32 + TB - 1) / TB, TB>>>(b0);

    // 7) support1 = fp16(h @ W1)  (tf32 mma.sync)
    gemm1_mma<<<(NN + 127) / 128, 256, SMEM_G1>>>(W1);

    // 8) out = spmm(adj1, support1) + b1  (fp32 out)
    spmm64_kernel<<<(NN * 32 + TB - 1) / TB, TB>>>(b1, (float2*)out);
}

// round 8
// speedup vs baseline: 2.7865x; 1.0172x over previous
#include <cuda_runtime.h>
#include <cuda_fp16.h>
#include <cstdint>

#define NN 50000
#define EE 800000
#define INF 128
#define HIDF 128
#define OUTF 64

#define SCAN_BLK 512
#define NBLK ((NN + SCAN_BLK - 1) / SCAN_BLK)   // 98

// ---------------- scratch (__device__ globals; no allocation allowed) ------
__device__ uint2    g_sup0h[NN * 32];   // fp16 support0 [NN][128]
__device__ uint2    g_hh[NN * 32];      // fp16 h        [NN][128]
__device__ uint32_t g_sup1h[NN * 32];   // fp16 support1 [NN][64]
__device__ int      g_cnt0[NN];         // zeroed at end of each run (scanB)
__device__ int      g_cnt1[NN];
__device__ int      g_ptr0[NN + 1];
__device__ int      g_ptr1[NN + 1];
__device__ int      g_cur0[NN];
__device__ int      g_cur1[NN];
__device__ int      g_bsum[2][NBLK];
__device__ int      g_boff[2][NBLK];
__device__ int      g_done0, g_done1;   // scanA arrival counters (self-reset)
__device__ int2     g_e0[EE];           // (col, val-bits) sorted by row
__device__ int2     g_e1[EE];

// ---------------- small helpers -------------------------------------------
__device__ __forceinline__ uint32_t f2tf32(float f) {
    uint32_t r;
    asm("cvt.rna.tf32.f32 %0, %1;" : "=r"(r) : "f"(f));
    return r;
}
__device__ __forceinline__ void mma_tf32(float& c0, float& c1, float& c2, float& c3,
                                         uint32_t a0, uint32_t a1, uint32_t a2, uint32_t a3,
                                         uint32_t b0, uint32_t b1) {
    asm volatile(
        "mma.sync.aligned.m16n8k8.row.col.f32.tf32.tf32.f32 "
        "{%0,%1,%2,%3}, {%4,%5,%6,%7}, {%8,%9}, {%0,%1,%2,%3};"
        : "+f"(c0), "+f"(c1), "+f"(c2), "+f"(c3)
        : "r"(a0), "r"(a1), "r"(a2), "r"(a3), "r"(b0), "r"(b1));
}

// ---------------- per-layer histogram (int4 vectorized, both layers) -------
__global__ void hist_kernel(const int* __restrict__ row0,
                            const int* __restrict__ row1) {
    int i = blockIdx.x * blockDim.x + threadIdx.x;
    if (i < EE / 4) {
        int4 r0 = ((const int4*)row0)[i];
        atomicAdd(&g_cnt0[r0.x], 1); atomicAdd(&g_cnt0[r0.y], 1);
        atomicAdd(&g_cnt0[r0.z], 1); atomicAdd(&g_cnt0[r0.w], 1);
        int4 r1 = ((const int4*)row1)[i];
        atomicAdd(&g_cnt1[r1.x], 1); atomicAdd(&g_cnt1[r1.y], 1);
        atomicAdd(&g_cnt1[r1.z], 1); atomicAdd(&g_cnt1[r1.w], 1);
    }
}

// ---------------- scanA: block-local scan + last-block scans block sums ----
__global__ void scanA_kernel() {
    __shared__ int s[SCAN_BLK];
    __shared__ int s_last;
    int which = blockIdx.y;
    const int* __restrict__ cnt = which ? g_cnt1 : g_cnt0;
    int* __restrict__ ptr = which ? g_ptr1 : g_ptr0;
    int tid = threadIdx.x;
    int i = blockIdx.x * SCAN_BLK + tid;
    int v = (i < NN) ? cnt[i] : 0;
    s[tid] = v;
    __syncthreads();
#pragma unroll
    for (int off = 1; off < SCAN_BLK; off <<= 1) {
        int t = (tid >= off) ? s[tid - off] : 0;
        __syncthreads();
        s[tid] += t;
        __syncthreads();
    }
    if (i < NN) ptr[i] = s[tid] - v;
    if (tid == SCAN_BLK - 1) g_bsum[which][blockIdx.x] = s[tid];
    __threadfence();
    if (tid == 0) {
        int* done = which ? &g_done1 : &g_done0;
        int d = atomicAdd(done, 1);
        s_last = (d == NBLK - 1);
        if (s_last) *done = 0;            // reset for next run
    }
    __syncthreads();
    if (!s_last) return;
    // this is the last-arriving block of this layer: scan the block sums
    __threadfence();                      // make all g_bsum writes visible
    __shared__ int s2[128];
    int v2 = 0;
    if (tid < 128) {
        v2 = (tid < NBLK) ? g_bsum[which][tid] : 0;
        s2[tid] = v2;
    }
    __syncthreads();
#pragma unroll
    for (int off = 1; off < 128; off <<= 1) {
        int t = (tid >= off && tid < 128) ? s2[tid - off] : 0;
        __syncthreads();
        if (tid < 128) s2[tid] += t;
        __syncthreads();
    }
    if (tid < NBLK) g_boff[which][tid] = s2[tid] - v2;
    if (tid == NBLK - 1) ptr[NN] = s2[tid];
}

// ---------------- scanB: add block offsets, init cursors, re-zero counts ---
__global__ void scanB_kernel() {
    int which = blockIdx.y;
    int* __restrict__ ptr = which ? g_ptr1 : g_ptr0;
    int* __restrict__ cur = which ? g_cur1 : g_cur0;
    int* __restrict__ cnt = which ? g_cnt1 : g_cnt0;
    int i = blockIdx.x * SCAN_BLK + threadIdx.x;
    if (i < NN) {
        int v = ptr[i] + g_boff[which][blockIdx.x];
        ptr[i] = v;
        cur[i] = v;
        cnt[i] = 0;                        // ready for next run's hist
    }
}

// ---------------- counting-sort scatter (both layers, int2 payload) --------
__global__ void scatter_kernel(const int* __restrict__ row0,
                               const int* __restrict__ col0,
                               const float* __restrict__ val0,
                               const int* __restrict__ row1,
                               const int* __restrict__ col1,
                               const float* __restrict__ val1) {
    int which = blockIdx.y;
    const int* __restrict__ row = which ? row1 : row0;
    const int* __restrict__ col = which ? col1 : col0;
    const int* __restrict__ val = (const int*)(which ? val1 : val0);
    int* __restrict__ cur = which ? g_cur1 : g_cur0;
    int2* __restrict__ ed = which ? g_e1 : g_e0;
    int i = blockIdx.x * blockDim.x + threadIdx.x;
    if (i < EE / 4) {
        int4 r = ((const int4*)row)[i];
        int4 c = ((const int4*)col)[i];
        int4 v = ((const int4*)val)[i];
        int p;
        p = atomicAdd(&cur[r.x], 1); ed[p] = make_int2(c.x, v.x);
        p = atomicAdd(&cur[r.y], 1); ed[p] = make_int2(c.y, v.y);
        p = atomicAdd(&cur[r.z], 1); ed[p] = make_int2(c.z, v.z);
        p = atomicAdd(&cur[r.w], 1); ed[p] = make_int2(c.w, v.w);
    }
}

// ---------------- GEMM 0: support0h = fp16( x @ W0 ), tf32 mma.sync --------
__global__ void __launch_bounds__(256, 1)
gemm0_mma(const float* __restrict__ x, const float* __restrict__ W0) {
    constexpr int NC = HIDF;
    constexpr int SA = 132, SB = NC + 8, WN = NC / 2, NT = WN / 8;
    extern __shared__ float sm[];
    float* As = sm; float* Bs = sm + 128 * SA;
    int tid = threadIdx.x, wid = tid >> 5, lane = tid & 31;
    int m0 = blockIdx.x * 128;
    int wm = (wid & 3) * 32, wn = (wid >> 2) * WN;
    int r = lane >> 2, cq = lane & 3;
    const float4* A4 = (const float4*)x;
#pragma unroll
    for (int it = 0; it < 16; it++) {
        int idx = it * 256 + tid;
        int rr = idx >> 5, c4 = idx & 31;
        float4 v = make_float4(0.f, 0.f, 0.f, 0.f);
        int gr = m0 + rr;
        if (gr < NN) v = A4[gr * 32 + c4];
        uint32_t* dst = (uint32_t*)&As[rr * SA + c4 * 4];
        dst[0] = f2tf32(v.x); dst[1] = f2tf32(v.y);
        dst[2] = f2tf32(v.z); dst[3] = f2tf32(v.w);
    }
    const float4* W4 = (const float4*)W0;
#pragma unroll
    for (int it = 0; it < (128 * NC / 4) / 256; it++) {
        int idx = it * 256 + tid;
        int kk = idx / (NC / 4), c4 = idx % (NC / 4);
        float4 v = W4[idx];
        uint32_t* dst = (uint32_t*)&Bs[kk * SB + c4 * 4];
        dst[0] = f2tf32(v.x); dst[1] = f2tf32(v.y);
        dst[2] = f2tf32(v.z); dst[3] = f2tf32(v.w);
    }
    __syncthreads();
    float acc[2][NT][4];
#pragma unroll
    for (int im = 0; im < 2; im++)
#pragma unroll
        for (int in = 0; in < NT; in++)
#pragma unroll
            for (int q = 0; q < 4; q++) acc[im][in][q] = 0.f;
    const uint32_t* Au = (const uint32_t*)As;
    const uint32_t* Bu = (const uint32_t*)Bs;
#pragma unroll
    for (int ks = 0; ks < 16; ks++) {
        int k0 = ks * 8;
        uint32_t a[2][4];
#pragma unroll
        for (int im = 0; im < 2; im++) {
            int base = wm + im * 16;
            a[im][0] = Au[(base + r) * SA + k0 + cq];
            a[im][1] = Au[(base + r + 8) * SA + k0 + cq];
            a[im][2] = Au[(base + r) * SA + k0 + cq + 4];
            a[im][3] = Au[(base + r + 8) * SA + k0 + cq + 4];
        }
#pragma unroll
        for (int in = 0; in < NT; in++) {
            int colx = wn + in * 8 + r;
            uint32_t b0 = Bu[(k0 + cq) * SB + colx];
            uint32_t b1 = Bu[(k0 + cq + 4) * SB + colx];
#pragma unroll
            for (int im = 0; im < 2; im++)
                mma_tf32(acc[im][in][0], acc[im][in][1], acc[im][in][2], acc[im][in][3],
                         a[im][0], a[im][1], a[im][2], a[im][3], b0, b1);
        }
    }
    __half2* C2 = (__half2*)g_sup0h;     // [NN][64] half2
#pragma unroll
    for (int im = 0; im < 2; im++) {
        int row = m0 + wm + im * 16 + r;
#pragma unroll
        for (int in = 0; in < NT; in++) {
            int colh = (wn + in * 8 + 2 * cq) >> 1;
            if (row < NN)
                C2[row * 64 + colh] = __floats2half2_rn(acc[im][in][0], acc[im][in][1]);
            if (row + 8 < NN)
                C2[(row + 8) * 64 + colh] = __floats2half2_rn(acc[im][in][2], acc[im][in][3]);
        }
    }
}

// ---------------- GEMM 1: support1h = fp16( h @ W1 ), tf32 mma.sync --------
__global__ void __launch_bounds__(256, 1)
gemm1_mma(const float* __restrict__ W1) {
    constexpr int NC = OUTF;
    constexpr int SA = 132, SB = NC + 8, WN = NC / 2, NT = WN / 8;
    extern __shared__ float sm[];
    float* As = sm; float* Bs = sm + 128 * SA;
    int tid = threadIdx.x, wid = tid >> 5, lane = tid & 31;
    int m0 = blockIdx.x * 128;
    int wm = (wid & 3) * 32, wn = (wid >> 2) * WN;
    int r = lane >> 2, cq = lane & 3;
#pragma unroll
    for (int it = 0; it < 16; it++) {
        int idx = it * 256 + tid;
        int rr = idx >> 5, c = idx & 31;
        uint2 t = make_uint2(0u, 0u);
        int gr = m0 + rr;
        if (gr < NN) t = g_hh[gr * 32 + c];
        float2 f0 = __half22float2(*(__half2*)&t.x);
        float2 f1 = __half22float2(*(__half2*)&t.y);
        uint32_t* dst = (uint32_t*)&As[rr * SA + c * 4];
        dst[0] = f2tf32(f0.x); dst[1] = f2tf32(f0.y);
        dst[2] = f2tf32(f1.x); dst[3] = f2tf32(f1.y);
    }
    const float4* W4 = (const float4*)W1;
#pragma unroll
    for (int it = 0; it < (128 * NC / 4) / 256; it++) {
        int idx = it * 256 + tid;
        int kk = idx / (NC / 4), c4 = idx % (NC / 4);
        float4 v = W4[idx];
        uint32_t* dst = (uint32_t*)&Bs[kk * SB + c4 * 4];
        dst[0] = f2tf32(v.x); dst[1] = f2tf32(v.y);
        dst[2] = f2tf32(v.z); dst[3] = f2tf32(v.w);
    }
    __syncthreads();
    float acc[2][NT][4];
#pragma unroll
    for (int im = 0; im < 2; im++)
#pragma unroll
        for (int in = 0; in < NT; in++)
#pragma unroll
            for (int q = 0; q < 4; q++) acc[im][in][q] = 0.f;
    const uint32_t* Au = (const uint32_t*)As;
    const uint32_t* Bu = (const uint32_t*)Bs;
#pragma unroll
    for (int ks = 0; ks < 16; ks++) {
        int k0 = ks * 8;
        uint32_t a[2][4];
#pragma unroll
        for (int im = 0; im < 2; im++) {
            int base = wm + im * 16;
            a[im][0] = Au[(base + r) * SA + k0 + cq];
            a[im][1] = Au[(base + r + 8) * SA + k0 + cq];
            a[im][2] = Au[(base + r) * SA + k0 + cq + 4];
            a[im][3] = Au[(base + r + 8) * SA + k0 + cq + 4];
        }
#pragma unroll
        for (int in = 0; in < NT; in++) {
            int colx = wn + in * 8 + r;
            uint32_t b0 = Bu[(k0 + cq) * SB + colx];
            uint32_t b1 = Bu[(k0 + cq + 4) * SB + colx];
#pragma unroll
            for (int im = 0; im < 2; im++)
                mma_tf32(acc[im][in][0], acc[im][in][1], acc[im][in][2], acc[im][in][3],
                         a[im][0], a[im][1], a[im][2], a[im][3], b0, b1);
        }
    }
    __half2* C2 = (__half2*)g_sup1h;     // [NN][32] half2
#pragma unroll
    for (int im = 0; im < 2; im++) {
        int row = m0 + wm + im * 16 + r;
#pragma unroll
        for (int in = 0; in < NT; in++) {
            int colh = (wn + in * 8 + 2 * cq) >> 1;
            if (row < NN)
                C2[row * 32 + colh] = __floats2half2_rn(acc[im][in][0], acc[im][in][1]);
            if (row + 8 < NN)
                C2[(row + 8) * 32 + colh] = __floats2half2_rn(acc[im][in][2], acc[im][in][3]);
        }
    }
}

// ---------------- CSR row-gather SpMM, F=128 fp16 in, fp16 out -------------
__global__ void spmm128_kernel(const float* __restrict__ bias) {
    int gtid = blockIdx.x * blockDim.x + threadIdx.x;
    int r = gtid >> 5;
    int lane = gtid & 31;
    if (r >= NN) return;
    int s = g_ptr0[r], e = g_ptr0[r + 1];
    float a0 = 0.f, a1 = 0.f, a2 = 0.f, a3 = 0.f;
    int i = s;
    for (; i + 1 < e; i += 2) {
        int2 ea = __ldg(&g_e0[i]);
        int2 eb = __ldg(&g_e0[i + 1]);
        uint2 ta = __ldg(&g_sup0h[ea.x * 32 + lane]);
        uint2 tb = __ldg(&g_sup0h[eb.x * 32 + lane]);
        float va = __int_as_float(ea.y), vb = __int_as_float(eb.y);
        float2 fa0 = __half22float2(*(__half2*)&ta.x);
        float2 fa1 = __half22float2(*(__half2*)&ta.y);
        float2 fb0 = __half22float2(*(__half2*)&tb.x);
        float2 fb1 = __half22float2(*(__half2*)&tb.y);
        a0 += va * fa0.x + vb * fb0.x; a1 += va * fa0.y + vb * fb0.y;
        a2 += va * fa1.x + vb * fb1.x; a3 += va * fa1.y + vb * fb1.y;
    }
    if (i < e) {
        int2 ea = __ldg(&g_e0[i]);
        float va = __int_as_float(ea.y);
        uint2 ta = __ldg(&g_sup0h[ea.x * 32 + lane]);
        float2 fa0 = __half22float2(*(__half2*)&ta.x);
        float2 fa1 = __half22float2(*(__half2*)&ta.y);
        a0 += va * fa0.x; a1 += va * fa0.y; a2 += va * fa1.x; a3 += va * fa1.y;
    }
    float4 b = ((const float4*)bias)[lane];
    a0 = fmaxf(a0 + b.x, 0.f); a1 = fmaxf(a1 + b.y, 0.f);
    a2 = fmaxf(a2 + b.z, 0.f); a3 = fmaxf(a3 + b.w, 0.f);
    uint2 o;
    *(__half2*)&o.x = __floats2half2_rn(a0, a1);
    *(__half2*)&o.y = __floats2half2_rn(a2, a3);
    g_hh[r * 32 + lane] = o;
}

// ---------------- CSR row-gather SpMM, F=64 fp16 in, fp32 out --------------
__global__ void spmm64_kernel(const float* __restrict__ bias,
                              float2* __restrict__ out2) {
    int gtid = blockIdx.x * blockDim.x + threadIdx.x;
    int r = gtid >> 5;
    int lane = gtid & 31;
    if (r >= NN) return;
    int s = g_ptr1[r], e = g_ptr1[r + 1];
    float a0 = 0.f, a1 = 0.f;
    int i = s;
    for (; i + 1 < e; i += 2) {
        int2 ea = __ldg(&g_e1[i]);
        int2 eb = __ldg(&g_e1[i + 1]);
        uint32_t ta = __ldg(&g_sup1h[ea.x * 32 + lane]);
        uint32_t tb = __ldg(&g_sup1h[eb.x * 32 + lane]);
        float va = __int_as_float(ea.y), vb = __int_as_float(eb.y);
        float2 fa = __half22float2(*(__half2*)&ta);
        float2 fb = __half22float2(*(__half2*)&tb);
        a0 += va * fa.x + vb * fb.x;
        a1 += va * fa.y + vb * fb.y;
    }
    if (i < e) {
        int2 ea = __ldg(&g_e1[i]);
        float va = __int_as_float(ea.y);
        uint32_t ta = __ldg(&g_sup1h[ea.x * 32 + lane]);
        float2 fa = __half22float2(*(__half2*)&ta);
        a0 += va * fa.x; a1 += va * fa.y;
    }
    float2 b = ((const float2*)bias)[lane];
    out2[r * 32 + lane] = make_float2(a0 + b.x, a1 + b.y);
}

// ---------------- launch (single stream, 8 kernels) ------------------------
extern "C" void kernel_launch(void* const* d_in, const int* in_sizes, int n_in,
                              void* d_out, int out_size) {
    const float* x    = (const float*)d_in[0];
    const int*   row0 = (const int*)d_in[1];
    const int*   col0 = (const int*)d_in[2];
    const float* val0 = (const float*)d_in[3];
    const int*   row1 = (const int*)d_in[4];
    const int*   col1 = (const int*)d_in[5];
    const float* val1 = (const float*)d_in[6];
    const float* W0   = (const float*)d_in[7];
    const float* b0   = (const float*)d_in[8];
    const float* W1   = (const float*)d_in[9];
    const float* b1   = (const float*)d_in[10];
    float* out = (float*)d_out;

    const int TB = 256;
    const int SMEM_G0 = 128 * 132 * 4 + 128 * (HIDF + 8) * 4;  // 137216
    const int SMEM_G1 = 128 * 132 * 4 + 128 * (OUTF + 8) * 4;  // 104448
    cudaFuncSetAttribute(gemm0_mma, cudaFuncAttributeMaxDynamicSharedMemorySize, SMEM_G0);
    cudaFuncSetAttribute(gemm1_mma, cudaFuncAttributeMaxDynamicSharedMemorySize, SMEM_G1);

    // 1) support0 = fp16(x @ W0)
    gemm0_mma<<<(NN + 127) / 128, 256, SMEM_G0>>>(x, W0);

    // 2) histogram both layers (counters pre-zeroed by previous run / static init)
    hist_kernel<<<(EE / 4 + TB - 1) / TB, TB>>>(row0, row1);

    // 3) scanA: local scans + last block scans block sums
    {
        dim3 g(NBLK, 2);
        scanA_kernel<<<g, SCAN_BLK>>>();
    }

    // 4) scanB: global offsets, cursors, re-zero counters
    {
        dim3 g(NBLK, 2);
        scanB_kernel<<<g, SCAN_BLK>>>();
    }

    // 5) counting-sort scatter (both layers)
    {
        dim3 gs((EE / 4 + TB - 1) / TB, 2);
        scatter_kernel<<<gs, TB>>>(row0, col0, val0, row1, col1, val1);
    }

    // 6) h = fp16(relu(spmm(adj0, support0) + b0))
    spmm128_kernel<<<(NN * 32 + TB - 1) / TB, TB>>>(b0);

    // 7) support1 = fp16(h @ W1)
    gemm1_mma<<<(NN + 127) / 128, 256, SMEM_G1>>>(W1);

    // 8) out = spmm(adj1, support1) + b1
    spmm64_kernel<<<(NN * 32 + TB - 1) / TB, TB>>>(b1, (float2*)out);
}